// round 1
// baseline (speedup 1.0000x reference)
#include <cuda_runtime.h>

#define BB    4096
#define TT    2048
#define DDIM  3
#define SDIM  5
#define HDIM  32
#define WPB   4                 // warps per block
#define CHUNK 32                // delta steps staged per smem refill
#define NCHUNK (TT / CHUNK)

// tanh(x) = 1 - 2/(exp2(2*log2(e)*x) + 1)  -- 5 instrs, 2 MUFU, ~1e-6 abs err.
// Large |x| saturates correctly (e -> inf => 1, e -> 0 => -1).
__device__ __forceinline__ float tanh_fast(float x) {
    float e, r;
    asm("ex2.approx.f32 %0, %1;" : "=f"(e) : "f"(x * 2.885390081777926815f));
    asm("rcp.approx.f32 %0, %1;" : "=f"(r) : "f"(e + 1.0f));
    return fmaf(-2.0f, r, 1.0f);
}

__global__ __launch_bounds__(WPB * 32, 7)
void msc_seq_kernel(const float* __restrict__ delta,
                    const float* __restrict__ state0,
                    const float* __restrict__ W1, const float* __restrict__ b1,
                    const float* __restrict__ W2, const float* __restrict__ b2,
                    const float* __restrict__ W3, const float* __restrict__ b3,
                    float* __restrict__ out)
{
    __shared__ __align__(16) float sh_h[WPB][2][HDIM];   // h1 double buffer per warp
    __shared__ float sh_d[WPB][CHUNK * DDIM];            // staged delta per warp

    const int lane = threadIdx.x & 31;
    const int warp = threadIdx.x >> 5;
    const int b    = blockIdx.x * WPB + warp;            // batch element owned by warp

    // ---- load weights into registers (lane j = hidden channel j) ----
    float w1r[8];
#pragma unroll
    for (int i = 0; i < 8; i++)  w1r[i] = W1[i * HDIM + lane];   // W1 column j
    float w2r[32];
#pragma unroll
    for (int i = 0; i < 32; i++) w2r[i] = W2[i * HDIM + lane];   // W2 column j
    float w3r[5];
#pragma unroll
    for (int k = 0; k < 5; k++)  w3r[k] = W3[lane * SDIM + k];   // W3 row j
    const float b1j = b1[lane];
    const float b2j = b2[lane];
    float b3s[5];
#pragma unroll
    for (int k = 0; k < 5; k++)  b3s[k] = b3[k] * 0.03125f;  // b3/32: butterfly over 32
                                                             // lanes re-sums it exactly

    // state is warp-uniform (every lane holds the full 5-vector)
    float st[5];
#pragma unroll
    for (int k = 0; k < 5; k++)  st[k] = state0[b * SDIM + k];

    const float* dptr = delta + (size_t)b * (TT * DDIM);
    float*       optr = out   + (size_t)b * (TT * SDIM);

    // lane-select predicates for the 5-wide output store (hoisted)
    const bool q1 = (lane == 1), q2 = (lane == 2), q3 = (lane == 3), q4 = (lane == 4);

    // prefetch first delta chunk: lane L holds steps' floats [3L, 3L+2]
    float r0 = dptr[lane * 3 + 0];
    float r1 = dptr[lane * 3 + 1];
    float r2 = dptr[lane * 3 + 2];

    for (int c = 0; c < NCHUNK; c++) {
        __syncwarp();                       // prior chunk's delta reads done
        sh_d[warp][lane * 3 + 0] = r0;
        sh_d[warp][lane * 3 + 1] = r1;
        sh_d[warp][lane * 3 + 2] = r2;
        __syncwarp();
        if (c + 1 < NCHUNK) {               // prefetch next chunk into regs
            const float* np = dptr + (size_t)(c + 1) * (CHUNK * DDIM);
            r0 = np[lane * 3 + 0];
            r1 = np[lane * 3 + 1];
            r2 = np[lane * 3 + 2];
        }

#pragma unroll 2
        for (int tl = 0; tl < CHUNK; tl++) {
            const int buf = tl & 1;
            const float d0 = sh_d[warp][tl * 3 + 0];
            const float d1 = sh_d[warp][tl * 3 + 1];
            const float d2 = sh_d[warp][tl * 3 + 2];

            // ---- stage 1: h1_j = tanh([s;d] . W1[:,j] + b1_j) ----
            float a = b1j;
            a = fmaf(st[0], w1r[0], a);
            a = fmaf(st[1], w1r[1], a);
            a = fmaf(st[2], w1r[2], a);
            a = fmaf(st[3], w1r[3], a);
            a = fmaf(st[4], w1r[4], a);
            a = fmaf(d0,    w1r[5], a);
            a = fmaf(d1,    w1r[6], a);
            a = fmaf(d2,    w1r[7], a);
            const float h1v = tanh_fast(a);

            // broadcast h1 via smem (double-buffered: one syncwarp per step)
            sh_h[warp][buf][lane] = h1v;
            __syncwarp();

            // ---- stage 2: h2_j = tanh(h1 . W2[:,j] + b2_j) ----
            float acc = b2j;
            const float4* hp = (const float4*)(&sh_h[warp][buf][0]);
#pragma unroll
            for (int q = 0; q < 8; q++) {
                float4 v = hp[q];            // broadcast LDS.128
                acc = fmaf(v.x, w2r[4 * q + 0], acc);
                acc = fmaf(v.y, w2r[4 * q + 1], acc);
                acc = fmaf(v.z, w2r[4 * q + 2], acc);
                acc = fmaf(v.w, w2r[4 * q + 3], acc);
            }
            const float h2v = tanh_fast(acc);

            // ---- stage 3: s += h2 . W3 + b3 (butterfly; all lanes get the sum) ----
            float p0 = fmaf(h2v, w3r[0], b3s[0]);
            float p1 = fmaf(h2v, w3r[1], b3s[1]);
            float p2 = fmaf(h2v, w3r[2], b3s[2]);
            float p3 = fmaf(h2v, w3r[3], b3s[3]);
            float p4 = fmaf(h2v, w3r[4], b3s[4]);
#pragma unroll
            for (int off = 16; off > 0; off >>= 1) {
                p0 += __shfl_xor_sync(0xffffffffu, p0, off);
                p1 += __shfl_xor_sync(0xffffffffu, p1, off);
                p2 += __shfl_xor_sync(0xffffffffu, p2, off);
                p3 += __shfl_xor_sync(0xffffffffu, p3, off);
                p4 += __shfl_xor_sync(0xffffffffu, p4, off);
            }
            st[0] += p0; st[1] += p1; st[2] += p2; st[3] += p3; st[4] += p4;

            // ---- store s_t: lanes 0..4 each write one channel (20B, 1 STG) ----
            float v = st[0];
            v = q1 ? st[1] : v;
            v = q2 ? st[2] : v;
            v = q3 ? st[3] : v;
            v = q4 ? st[4] : v;
            if (lane < SDIM) optr[lane] = v;
            optr += SDIM;
        }
    }
}

extern "C" void kernel_launch(void* const* d_in, const int* in_sizes, int n_in,
                              void* d_out, int out_size)
{
    const float* delta  = (const float*)d_in[0];
    const float* state0 = (const float*)d_in[1];
    const float* W1     = (const float*)d_in[2];
    const float* b1     = (const float*)d_in[3];
    const float* W2     = (const float*)d_in[4];
    const float* b2     = (const float*)d_in[5];
    const float* W3     = (const float*)d_in[6];
    const float* b3     = (const float*)d_in[7];
    float* out = (float*)d_out;

    dim3 grid(BB / WPB);     // 1024 blocks of 4 warps -> 4096 warps, one per batch
    dim3 block(WPB * 32);
    msc_seq_kernel<<<grid, block>>>(delta, state0, W1, b1, W2, b2, W3, b3, out);
}